// round 15
// baseline (speedup 1.0000x reference)
#include <cuda_runtime.h>

#define CC 64
#define BB 32
#define HH 80
#define WW 80
#define CELL (CC*BB)      // 2048 floats per cell tile
#define NCELLS (HH*WW)    // 6400 cells
#define GS 68             // float G smem row stride (16B-aligned)
#define HS 20             // h buffer row stride in floats

// Static device scratch (allocation-free per harness rules)
__device__ float g_xT[NCELLS*CELL];          // x transposed to [i][j][c][b]
__device__ float g_hf[4][NCELLS*CELL];       // per-direction h fields, [i][j][c][b]
__device__ int   g_cnt[4][WW][4];            // per-(dir,col,(cpart,half)) rows-completed flags

typedef unsigned long long ull;

// ---------- packed-f32x2 helpers ----------
static __device__ __forceinline__ ull splat2(float x){
  unsigned int r = __float_as_uint(x);
  ull d; asm("mov.b64 %0, {%1,%2};" : "=l"(d) : "r"(r), "r"(r));
  return d;
}
static __device__ __forceinline__ void fma2(ull &d, ull a, ull b){
  asm("fma.rn.f32x2 %0, %1, %2, %0;" : "+l"(d) : "l"(a), "l"(b));
}
static __device__ __forceinline__ void add2(ull &d, ull a){
  asm("add.rn.f32x2 %0, %0, %1;" : "+l"(d) : "l"(a));
}
static __device__ __forceinline__ void unpack2(ull v, float &lo, float &hi){
  unsigned int a, b;
  asm("mov.b64 {%0,%1}, %2;" : "=r"(a), "=r"(b) : "l"(v));
  lo = __uint_as_float(a); hi = __uint_as_float(b);
}
static __device__ __forceinline__ int ld_acq(const int* p){
  int v; asm volatile("ld.global.acquire.gpu.b32 %0, [%1];" : "=r"(v) : "l"(p)); return v;
}
static __device__ __forceinline__ void st_rel(int* p, int v){
  asm volatile("st.global.release.gpu.b32 [%0], %1;" :: "l"(p), "r"(v));
}
static __device__ __forceinline__ void bar64(int id){
  asm volatile("bar.sync %0, 64;" :: "r"(id) : "memory");
}
static __device__ __forceinline__ void bar128_sync(int id){
  asm volatile("bar.sync %0, 128;" :: "r"(id) : "memory");
}
static __device__ __forceinline__ void bar128_arrive(int id){
  asm volatile("bar.arrive %0, 128;" :: "r"(id) : "memory");
}

// ---------- dummy kernel: shifts ncu's -s 5 window onto k_dag ----------
__global__ void k_nop(){}

// ---------- kernel 1: transpose x [B,C,H,W] -> g_xT [i][j][c][b]; zero flags ----------
__global__ void __launch_bounds__(256) k_transpose(const float* __restrict__ x){
  int bid = blockIdx.x;              // 800 blocks: (i, j-tile of 8)
  int i  = bid / 10;
  int j0 = (bid % 10) * 8;
  int t  = threadIdx.x;

  if (bid == 0){
    for (int z = t; z < 4*WW*4; z += 256) ((int*)g_cnt)[z] = 0;
  }

  int p0 = t * 8;                    // p = c*32 + b ; 8 consecutive p = fixed c, 8 b's
  int c  = p0 >> 5;
  int b0 = p0 & 31;

  float v[8][8];
  #pragma unroll
  for (int pi = 0; pi < 8; pi++){
    const float* src = x + (((b0+pi)*CC + c)*HH + i)*WW + j0;
    float4 q0 = *(const float4*)src;
    float4 q1 = *(const float4*)(src + 4);
    v[pi][0]=q0.x; v[pi][1]=q0.y; v[pi][2]=q0.z; v[pi][3]=q0.w;
    v[pi][4]=q1.x; v[pi][5]=q1.y; v[pi][6]=q1.z; v[pi][7]=q1.w;
  }
  #pragma unroll
  for (int jj = 0; jj < 8; jj++){
    float* dst = g_xT + (i*WW + j0 + jj)*CELL + p0;
    *(float4*)dst     = make_float4(v[0][jj], v[1][jj], v[2][jj], v[3][jj]);
    *(float4*)(dst+4) = make_float4(v[4][jj], v[5][jj], v[6][jj], v[7][jj]);
  }
}

// ---------- inner matmul over k-range [K0, K0+KN) ----------
// Warp tile 32c x 16b; lane = (cg=lane>>2) x (bp=lane&3); thread tile 4c x 4b.
// Acc layout: a[r][0] = row c0+r x (b0,b0+1) ; a[r][1] = row c0+r x (b0+2,b0+3).
template<int K0, int KN>
static __device__ __forceinline__ void mm_rng(const float* __restrict__ sG,
    const float* __restrict__ hb, int c0, int bloc, ull a[4][2]){
  #pragma unroll 8
  for (int k = K0; k < K0 + KN; k++){
    float4 gq = *(const float4*)(sG + k*GS + c0);           // G[c0..c0+3][k]
    ulonglong2 hq = *(const ulonglong2*)(hb + k*HS + bloc); // pairs (b0,b0+1),(b0+2,b0+3)
    ull g0 = splat2(gq.x), g1 = splat2(gq.y), g2 = splat2(gq.z), g3 = splat2(gq.w);
    fma2(a[0][0], g0, hq.x); fma2(a[0][1], g0, hq.y);
    fma2(a[1][0], g1, hq.x); fma2(a[1][1], g1, hq.y);
    fma2(a[2][0], g2, hq.x); fma2(a[2][1], g2, hq.y);
    fma2(a[3][0], g3, hq.x); fma2(a[3][1], g3, hq.y);
  }
}

// ---------- kernel 2: persistent DAG recurrence; role-split + k-split Gh ----------
// CTA = (dir, column), 256 thr. w = role*4 + cpart*2 + half.
// role 1 (h): poll flag ; stage hB(parity) ; signal ; Gh over k=0..31 ; STS partial.
// role 0 (v): acc = x + Gv@hA ; wait signal ; Gh over k=32..63 into acc ; merge partial ;
//             relu ; publish ; release ; writeback hA.
extern __shared__ float smem_dyn[];

__global__ void __launch_bounds__(256, 3) k_dag(
    const float* __restrict__ w0v, const float* __restrict__ w0h,
    const float* __restrict__ w1v, const float* __restrict__ w1h,
    const float* __restrict__ w2v, const float* __restrict__ w2h,
    const float* __restrict__ w3v, const float* __restrict__ w3h)
{
  const int bid  = blockIdx.x;
  const int dir  = bid & 3;          // interleaved: dep (dir,jcol-1) = bid-4 < bid
  const int jcol = bid >> 2;
  const int tid  = threadIdx.x;

  const float* gvp; const float* ghp;
  int fi, fj, doRelu;
  switch (dir){
    case 0:  gvp=w0v; ghp=w0h; fi=0; fj=0; doRelu=1; break;  // SE
    case 1:  gvp=w1v; ghp=w1h; fi=1; fj=0; doRelu=1; break;  // NE
    case 2:  gvp=w2v; ghp=w2h; fi=1; fj=1; doRelu=1; break;  // NW
    default: gvp=w3v; ghp=w3h; fi=0; fj=1; doRelu=0; break;  // SW (no ReLU in reference)
  }

  float* sGv   = smem_dyn;                       // [k][c] float, CC*GS (17,408 B each)
  float* sGh   = sGv + CC*GS;
  float* hAb   = sGh + CC*GS;                    // [half][CC][HS]  (2 x 5,120 B)
  float* hBb   = hAb + 2*CC*HS;                  // [half][parity][CC][HS] (4 x 5,120 B)
  ull*   Pb    = (ull*)(hBb + 4*CC*HS);          // partial: [q][256] ull (8,192 B)

  for (int idx = tid; idx < 4096; idx += 256){
    int c = idx >> 6, k = idx & 63;              // idx = c*64 + k (row-major source)
    sGv[k*GS + c] = gvp[idx];
    sGh[k*GS + c] = ghp[idx];
  }
  for (int idx = tid; idx < 2*CC*HS; idx += 256) hAb[idx] = 0.f;   // zero vertical state
  __syncthreads();

  const int lane  = tid & 31, w = tid >> 5;
  const int role  = w >> 2, cpart = (w >> 1) & 1, half = w & 1;
  const int cg = lane >> 2, bp = lane & 3;
  const int c0   = cpart*32 + cg*4;
  const int bloc = bp*4;                         // local b within 16-wide half
  const int b0g  = half*16 + bloc;               // global b
  const int tRow = cpart*32 + lane;              // h-warp staging k-row

  float* hA = hAb + half*CC*HS;
  ull* Ptile = Pb + (cpart*2 + half)*256;

  float* out_dir = g_hf[dir];
  const int rj  = fj ? (WW-1-jcol) : jcol;
  const int rjL = fj ? (WW-jcol)   : (jcol-1);
  const int q = cpart*2 + half;                  // flag slot (same formula producer+consumer)
  const int* pflag = &g_cnt[dir][(jcol > 0) ? (jcol-1) : 0][q];
  int* mflag = &g_cnt[dir][jcol][q];
  const bool hasLeft = (jcol > 0);

  const int idV = 1 + half;                      // v-pair bar (64 thr)
  const int idR = 3 + half;                      // hB-ready: h arrive / v sync (128 thr)
  const int idH = 5 + half;                      // h-pair staging bar (64 thr)
  const int idB = 7 + q;                         // partial ready (v+h pair, 64 thr)
  const int idA = 11 + q;                        // partial consumed (v+h pair, 64 thr)

  if (role == 1){
    // ================= h-warps =================
    if (!hasLeft) return;                        // column 0 has no horizontal term
    for (int i = 0; i < HH; i++){
      const int ri = fi ? (HH-1-i) : i;

      // poll producer flag (one address), then stage its 32-row slice into parity buffer
      const int need = i + 1;
      while (ld_acq(pflag) < need) { }
      const float* src = out_dir + (ri*WW + rjL)*CELL + tRow*BB + half*16;
      float4 l0 = *(const float4*)(src);
      float4 l1 = *(const float4*)(src + 4);
      float4 l2 = *(const float4*)(src + 8);
      float4 l3 = *(const float4*)(src + 12);
      float* hBp = hBb + (half*2 + (i&1))*CC*HS;
      float* dst = hBp + tRow*HS;
      *(float4*)(dst + 0)  = l0;
      *(float4*)(dst + 4)  = l1;
      *(float4*)(dst + 8)  = l2;
      *(float4*)(dst + 12) = l3;
      bar64(idH);                                // both h-warps staged -> hB(parity) complete
      bar128_arrive(idR);                        // signal v-pair (non-blocking)

      ull hacc[4][2] = {{0,0},{0,0},{0,0},{0,0}};
      mm_rng<0,32>(sGh, hBp, c0, bloc, hacc);    // chain-critical half matmul

      if (i > 0) bar64(idA);                     // v finished reading partial(i-1)
      #pragma unroll
      for (int u = 0; u < 8; u++)                // conflict-free STS.64
        Ptile[u*32 + lane] = hacc[u>>1][u&1];
      bar64(idB);                                // partial(i) ready
    }
    return;
  }

  // ================= v-warps =================
  ulonglong2 xp[4];
  {
    const int ri0 = fi ? (HH-1) : 0;
    const float* xc = g_xT + (ri0*WW + rj)*CELL;
    #pragma unroll
    for (int r = 0; r < 4; r++)
      xp[r] = *(const ulonglong2*)(xc + (c0+r)*BB + b0g);
  }

  for (int i = 0; i < HH; i++){
    const int ri = fi ? (HH-1-i) : i;

    bar64(idV);                                  // partner v-warp writeback(i-1) visible

    ull a[4][2];
    #pragma unroll
    for (int r = 0; r < 4; r++){ a[r][0] = xp[r].x; a[r][1] = xp[r].y; }
    mm_rng<0,CC>(sGv, hA, c0, bloc, a);          // full vertical matmul (off-chain)

    // prefetch x for next row (hidden under handoff waits)
    if (i + 1 < HH){
      const int rin = fi ? (HH-2-i) : (i+1);
      const float* xc = g_xT + (rin*WW + rj)*CELL;
      #pragma unroll
      for (int r = 0; r < 4; r++)
        xp[r] = *(const ulonglong2*)(xc + (c0+r)*BB + b0g);
    }

    bar64(idV);                                  // partner done reading hA -> writeback safe below

    if (hasLeft){
      bar128_sync(idR);                          // hB(parity) fully staged by h-pair
      const float* hBp = hBb + (half*2 + (i&1))*CC*HS;
      mm_rng<32,32>(sGh, hBp, c0, bloc, a);      // v's k-half of the horizontal matmul
      bar64(idB);                                // h partial (k 0..31) ready
      #pragma unroll
      for (int u = 0; u < 8; u++){
        ull p = Ptile[u*32 + lane];
        add2(a[u>>1][u&1], p);
      }
    }

    // epilogue: unpack, ReLU
    float o[4][4];                               // o[r][bb] = h[c0+r][b0g+bb]
    #pragma unroll
    for (int r = 0; r < 4; r++){
      unpack2(a[r][0], o[r][0], o[r][1]);
      unpack2(a[r][1], o[r][2], o[r][3]);
    }
    if (doRelu){
      #pragma unroll
      for (int r = 0; r < 4; r++)
        #pragma unroll
        for (int bb = 0; bb < 4; bb++)
          o[r][bb] = fmaxf(o[r][bb], 0.f);
    }

    // publish to gmem, release per-tile flag
    float* ocell = out_dir + (ri*WW + rj)*CELL;
    #pragma unroll
    for (int r = 0; r < 4; r++)
      *(float4*)(ocell + (c0+r)*BB + b0g) = make_float4(o[r][0], o[r][1], o[r][2], o[r][3]);
    __syncwarp();                                // order warp's STGs before lane0's release
    if (lane == 0) st_rel(mflag, i + 1);

    // vertical state writeback (safe: both v-warps past 2nd idV)
    #pragma unroll
    for (int r = 0; r < 4; r++)
      *(float4*)(hA + (c0+r)*HS + bloc) = make_float4(o[r][0], o[r][1], o[r][2], o[r][3]);

    if (hasLeft && i + 1 < HH) bar64(idA);       // signal: partial(i) + hB(parity i) consumed
  }
}

// ---------- kernel 3: out[b][c][i][j] = sum over 4 dirs of g_hf[d][i][j][c][b] ----------
__global__ void __launch_bounds__(256) k_sum(float* __restrict__ out){
  int bid = blockIdx.x;              // 800 blocks: (i, j-tile of 8)
  int i  = bid / 10;
  int j0 = (bid % 10) * 8;
  int t  = threadIdx.x;
  int p0 = t * 8;                    // fixed c, 8 consecutive b
  int c  = p0 >> 5;
  int b0 = p0 & 31;

  float v[8][8];
  #pragma unroll
  for (int jj = 0; jj < 8; jj++){
    int cell = (i*WW + j0 + jj)*CELL;
    float4 s0 = make_float4(0.f,0.f,0.f,0.f);
    float4 s1 = make_float4(0.f,0.f,0.f,0.f);
    #pragma unroll
    for (int d = 0; d < 4; d++){
      const float* src = g_hf[d] + cell + p0;
      float4 q0 = *(const float4*)src;
      float4 q1 = *(const float4*)(src + 4);
      s0.x += q0.x; s0.y += q0.y; s0.z += q0.z; s0.w += q0.w;
      s1.x += q1.x; s1.y += q1.y; s1.z += q1.z; s1.w += q1.w;
    }
    v[0][jj]=s0.x; v[1][jj]=s0.y; v[2][jj]=s0.z; v[3][jj]=s0.w;
    v[4][jj]=s1.x; v[5][jj]=s1.y; v[6][jj]=s1.z; v[7][jj]=s1.w;
  }
  #pragma unroll
  for (int pi = 0; pi < 8; pi++){
    float* dst = out + ((b0+pi)*CC + c)*NCELLS + i*WW + j0;
    *(float4*)dst     = make_float4(v[pi][0], v[pi][1], v[pi][2], v[pi][3]);
    *(float4*)(dst+4) = make_float4(v[pi][4], v[pi][5], v[pi][6], v[pi][7]);
  }
}

extern "C" void kernel_launch(void* const* d_in, const int* in_sizes, int n_in,
                              void* d_out, int out_size){
  const float* x   = (const float*)d_in[0];
  const float* g1  = (const float*)d_in[1];
  const float* g2  = (const float*)d_in[2];
  const float* g4  = (const float*)d_in[3];
  const float* g5  = (const float*)d_in[4];
  const float* g7  = (const float*)d_in[5];
  const float* g8  = (const float*)d_in[6];
  const float* g10 = (const float*)d_in[7];
  const float* g11 = (const float*)d_in[8];

  // G 34,816 + hA 10,240 + hB 20,480 + partial 8,192 = 73,728 B -> 3 CTAs/SM
  const int smem_bytes = 2*CC*GS*4 + 2*CC*HS*4 + 4*CC*HS*4 + 4*256*8;
  (void)cudaFuncSetAttribute(k_dag, cudaFuncAttributeMaxDynamicSharedMemorySize, smem_bytes);

  // two no-op launches: shift ncu's (-s 5 -c 1) capture window onto k_dag
  k_nop<<<1, 1>>>();
  k_nop<<<1, 1>>>();
  k_transpose<<<800, 256>>>(x);
  k_dag<<<4*WW, 256, smem_bytes>>>(g1, g2, g4, g5, g7, g8, g10, g11);
  k_sum<<<800, 256>>>((float*)d_out);
}

// round 16
// speedup vs baseline: 1.0799x; 1.0799x over previous
#include <cuda_runtime.h>

#define CC 64
#define BB 32
#define HH 80
#define WW 80
#define CELL (CC*BB)      // 2048 floats per cell tile
#define NCELLS (HH*WW)    // 6400 cells
#define GS 68             // float G smem row stride (16B-aligned)
#define HS 20             // h buffer row stride in floats

// Static device scratch (allocation-free per harness rules)
__device__ float g_xT[NCELLS*CELL];          // x transposed to [i][j][c][b]
__device__ float g_hf[4][NCELLS*CELL];       // per-direction h fields, [i][j][c][b]
__device__ int   g_cnt[4][WW][4];            // per-(dir,col,(cpart,half)) rows-completed flags

typedef unsigned long long ull;

// ---------- packed-f32x2 helpers ----------
static __device__ __forceinline__ ull splat2(float x){
  unsigned int r = __float_as_uint(x);
  ull d; asm("mov.b64 %0, {%1,%2};" : "=l"(d) : "r"(r), "r"(r));
  return d;
}
static __device__ __forceinline__ void fma2(ull &d, ull a, ull b){
  asm("fma.rn.f32x2 %0, %1, %2, %0;" : "+l"(d) : "l"(a), "l"(b));
}
static __device__ __forceinline__ void add2(ull &d, ull a){
  asm("add.rn.f32x2 %0, %0, %1;" : "+l"(d) : "l"(a));
}
static __device__ __forceinline__ void unpack2(ull v, float &lo, float &hi){
  unsigned int a, b;
  asm("mov.b64 {%0,%1}, %2;" : "=r"(a), "=r"(b) : "l"(v));
  lo = __uint_as_float(a); hi = __uint_as_float(b);
}
static __device__ __forceinline__ int ld_acq(const int* p){
  int v; asm volatile("ld.global.acquire.gpu.b32 %0, [%1];" : "=r"(v) : "l"(p)); return v;
}
static __device__ __forceinline__ void st_rel(int* p, int v){
  asm volatile("st.global.release.gpu.b32 [%0], %1;" :: "l"(p), "r"(v));
}
static __device__ __forceinline__ void bar64(int id){
  asm volatile("bar.sync %0, 64;" :: "r"(id) : "memory");
}
static __device__ __forceinline__ void bar128_sync(int id){
  asm volatile("bar.sync %0, 128;" :: "r"(id) : "memory");
}
static __device__ __forceinline__ void bar128_arrive(int id){
  asm volatile("bar.arrive %0, 128;" :: "r"(id) : "memory");
}

// ---------- dummy kernel: shifts ncu's -s 5 window onto k_dag ----------
__global__ void k_nop(){}

// ---------- kernel 1: transpose x [B,C,H,W] -> g_xT [i][j][c][b]; zero flags ----------
__global__ void __launch_bounds__(256) k_transpose(const float* __restrict__ x){
  int bid = blockIdx.x;              // 800 blocks: (i, j-tile of 8)
  int i  = bid / 10;
  int j0 = (bid % 10) * 8;
  int t  = threadIdx.x;

  if (bid == 0){
    for (int z = t; z < 4*WW*4; z += 256) ((int*)g_cnt)[z] = 0;
  }

  int p0 = t * 8;                    // p = c*32 + b ; 8 consecutive p = fixed c, 8 b's
  int c  = p0 >> 5;
  int b0 = p0 & 31;

  float v[8][8];
  #pragma unroll
  for (int pi = 0; pi < 8; pi++){
    const float* src = x + (((b0+pi)*CC + c)*HH + i)*WW + j0;
    float4 q0 = *(const float4*)src;
    float4 q1 = *(const float4*)(src + 4);
    v[pi][0]=q0.x; v[pi][1]=q0.y; v[pi][2]=q0.z; v[pi][3]=q0.w;
    v[pi][4]=q1.x; v[pi][5]=q1.y; v[pi][6]=q1.z; v[pi][7]=q1.w;
  }
  #pragma unroll
  for (int jj = 0; jj < 8; jj++){
    float* dst = g_xT + (i*WW + j0 + jj)*CELL + p0;
    *(float4*)dst     = make_float4(v[0][jj], v[1][jj], v[2][jj], v[3][jj]);
    *(float4*)(dst+4) = make_float4(v[4][jj], v[5][jj], v[6][jj], v[7][jj]);
  }
}

// ---------- 32-k inner matmul (pre-offset base pointers select the k-range) ----------
// Warp tile 32c x 16b; lane = (cg=lane>>2) x (bp=lane&3); thread tile 4c x 4b.
// Acc layout: a[r][0] = row c0+r x (b0,b0+1) ; a[r][1] = row c0+r x (b0+2,b0+3).
static __device__ __forceinline__ void mm32(const float* __restrict__ sG,
    const float* __restrict__ hb, int c0, int bloc, ull a[4][2]){
  #pragma unroll 8
  for (int k = 0; k < 32; k++){
    float4 gq = *(const float4*)(sG + k*GS + c0);           // G[c0..c0+3][k]
    ulonglong2 hq = *(const ulonglong2*)(hb + k*HS + bloc); // pairs (b0,b0+1),(b0+2,b0+3)
    ull g0 = splat2(gq.x), g1 = splat2(gq.y), g2 = splat2(gq.z), g3 = splat2(gq.w);
    fma2(a[0][0], g0, hq.x); fma2(a[0][1], g0, hq.y);
    fma2(a[1][0], g1, hq.x); fma2(a[1][1], g1, hq.y);
    fma2(a[2][0], g2, hq.x); fma2(a[2][1], g2, hq.y);
    fma2(a[3][0], g3, hq.x); fma2(a[3][1], g3, hq.y);
  }
}

// ---------- kernel 2: persistent DAG recurrence; balanced role-split (896/896 instr) ----------
// CTA = (dir, column), 256 thr. w = role*4 + cpart*2 + half.  q = cpart*2+half.
// h_X: [idA] ; Gv k[X*32..) ; poll ; stage rows [X*32..) ; syncwarp ; arrive idR ;
//      Gh k[X*32..) (own staged rows) ; STS partial(Gv+Gh) ; idB.
// v_X: idV ; acc = x + Gv k[(1-X)*32..) ; prefetch ; idV ; idR ; Gh k[(1-X)*32..) ;
//      idB ; merge ; relu ; publish ; release ; writeback hA ; arrive idA.
extern __shared__ float smem_dyn[];

__global__ void __launch_bounds__(256, 3) k_dag(
    const float* __restrict__ w0v, const float* __restrict__ w0h,
    const float* __restrict__ w1v, const float* __restrict__ w1h,
    const float* __restrict__ w2v, const float* __restrict__ w2h,
    const float* __restrict__ w3v, const float* __restrict__ w3h)
{
  const int bid  = blockIdx.x;
  const int dir  = bid & 3;          // interleaved: dep (dir,jcol-1) = bid-4 < bid
  const int jcol = bid >> 2;
  const int tid  = threadIdx.x;

  const float* gvp; const float* ghp;
  int fi, fj, doRelu;
  switch (dir){
    case 0:  gvp=w0v; ghp=w0h; fi=0; fj=0; doRelu=1; break;  // SE
    case 1:  gvp=w1v; ghp=w1h; fi=1; fj=0; doRelu=1; break;  // NE
    case 2:  gvp=w2v; ghp=w2h; fi=1; fj=1; doRelu=1; break;  // NW
    default: gvp=w3v; ghp=w3h; fi=0; fj=1; doRelu=0; break;  // SW (no ReLU in reference)
  }

  float* sGv   = smem_dyn;                       // [k][c] float, CC*GS (17,408 B each)
  float* sGh   = sGv + CC*GS;
  float* hAb   = sGh + CC*GS;                    // [half][CC][HS]  (2 x 5,120 B)
  float* hBb   = hAb + 2*CC*HS;                  // [half][parity][CC][HS] (4 x 5,120 B)
  ull*   Pb    = (ull*)(hBb + 4*CC*HS);          // partial: [q][256] ull (8,192 B)

  for (int idx = tid; idx < 4096; idx += 256){
    int c = idx >> 6, k = idx & 63;              // idx = c*64 + k (row-major source)
    sGv[k*GS + c] = gvp[idx];
    sGh[k*GS + c] = ghp[idx];
  }
  for (int idx = tid; idx < 2*CC*HS; idx += 256) hAb[idx] = 0.f;   // zero vertical state
  __syncthreads();

  const int lane  = tid & 31, w = tid >> 5;
  const int role  = w >> 2, cpart = (w >> 1) & 1, half = w & 1;
  const int cg = lane >> 2, bp = lane & 3;
  const int c0   = cpart*32 + cg*4;
  const int bloc = bp*4;                         // local b within 16-wide half
  const int b0g  = half*16 + bloc;               // global b
  const int tRow = cpart*32 + lane;              // h-warp staging k-row

  float* hA = hAb + half*CC*HS;
  ull* Ptile = Pb + (cpart*2 + half)*256;

  float* out_dir = g_hf[dir];
  const int rj  = fj ? (WW-1-jcol) : jcol;
  const int rjL = fj ? (WW-jcol)   : (jcol-1);
  const int q = cpart*2 + half;                  // flag slot (same formula producer+consumer)
  const int* pflag = &g_cnt[dir][(jcol > 0) ? (jcol-1) : 0][q];
  int* mflag = &g_cnt[dir][jcol][q];
  const bool hasLeft = (jcol > 0);

  const int idV = 1 + half;                      // v-pair bar (64 thr)
  const int idR = 3 + half;                      // hB-ready: h arrive / v sync (128 thr)
  const int idB = 5 + q;                         // partial ready (v+h pair, 64 thr)
  const int idA = 9 + q;                         // row closed: hA written + partial consumed

  if (role == 1){
    // ================= h-warps =================
    if (!hasLeft) return;                        // column 0 has no horizontal term
    const int kh = cpart*32;                     // own k-range base (Gv, staging, Gh)
    const float* sGv_h = sGv + kh*GS;
    const float* sGh_h = sGh + kh*GS;
    const float* hA_h  = hA + kh*HS;
    for (int i = 0; i < HH; i++){
      const int ri = fi ? (HH-1-i) : i;

      if (i > 0) bar64(idA);                     // v row i-1 closed: hA(i-1) ready, partial free

      ull hacc[4][2] = {{0,0},{0,0},{0,0},{0,0}};
      mm32(sGv_h, hA_h, c0, bloc, hacc);         // Gv own k-half (hidden in wavefront wait)

      // poll producer flag, stage own 32-row slice into parity buffer
      const int need = i + 1;
      while (ld_acq(pflag) < need) { }
      const float* src = out_dir + (ri*WW + rjL)*CELL + tRow*BB + half*16;
      float4 l0 = *(const float4*)(src);
      float4 l1 = *(const float4*)(src + 4);
      float4 l2 = *(const float4*)(src + 8);
      float4 l3 = *(const float4*)(src + 12);
      float* hBp = hBb + (half*2 + (i&1))*CC*HS;
      float* dst = hBp + tRow*HS;
      *(float4*)(dst + 0)  = l0;
      *(float4*)(dst + 4)  = l1;
      *(float4*)(dst + 8)  = l2;
      *(float4*)(dst + 12) = l3;
      __syncwarp();                              // own staging visible warp-wide
      bar128_arrive(idR);                        // signal v-pair (non-blocking)

      mm32(sGh_h, hBp + kh*HS, c0, bloc, hacc);  // Gh own k-half (own staged rows only)

      #pragma unroll
      for (int u = 0; u < 8; u++)                // conflict-free STS.64
        Ptile[u*32 + lane] = hacc[u>>1][u&1];
      bar64(idB);                                // partial(i) ready
    }
    return;
  }

  // ================= v-warps =================
  const int kv = (1-cpart)*32;                   // complement k-range base
  const float* sGv_v = sGv + kv*GS;
  const float* sGh_v = sGh + kv*GS;
  const float* hA_v  = hA + kv*HS;

  ulonglong2 xp[4];
  {
    const int ri0 = fi ? (HH-1) : 0;
    const float* xc = g_xT + (ri0*WW + rj)*CELL;
    #pragma unroll
    for (int r = 0; r < 4; r++)
      xp[r] = *(const ulonglong2*)(xc + (c0+r)*BB + b0g);
  }

  for (int i = 0; i < HH; i++){
    const int ri = fi ? (HH-1-i) : i;

    bar64(idV);                                  // partner v-warp writeback(i-1) visible

    ull a[4][2];
    #pragma unroll
    for (int r = 0; r < 4; r++){ a[r][0] = xp[r].x; a[r][1] = xp[r].y; }
    if (hasLeft){
      mm32(sGv_v, hA_v, c0, bloc, a);            // Gv complement k-half
    } else {
      mm32(sGv, hA, c0, bloc, a);                // column 0: full Gv
      mm32(sGv + 32*GS, hA + 32*HS, c0, bloc, a);
    }

    // prefetch x for next row (hidden under handoff waits)
    if (i + 1 < HH){
      const int rin = fi ? (HH-2-i) : (i+1);
      const float* xc = g_xT + (rin*WW + rj)*CELL;
      #pragma unroll
      for (int r = 0; r < 4; r++)
        xp[r] = *(const ulonglong2*)(xc + (c0+r)*BB + b0g);
    }

    bar64(idV);                                  // partner done reading hA -> writeback safe below

    if (hasLeft){
      bar128_sync(idR);                          // hB(parity) fully staged by h-pair
      const float* hBp = hBb + (half*2 + (i&1))*CC*HS;
      mm32(sGh_v, hBp + kv*HS, c0, bloc, a);     // Gh complement (staged by other h-warp)
      bar64(idB);                                // partial (Gv+Gh own halves) ready
      #pragma unroll
      for (int u = 0; u < 8; u++){
        ull p = Ptile[u*32 + lane];
        add2(a[u>>1][u&1], p);
      }
    }

    // epilogue: unpack, ReLU
    float o[4][4];                               // o[r][bb] = h[c0+r][b0g+bb]
    #pragma unroll
    for (int r = 0; r < 4; r++){
      unpack2(a[r][0], o[r][0], o[r][1]);
      unpack2(a[r][1], o[r][2], o[r][3]);
    }
    if (doRelu){
      #pragma unroll
      for (int r = 0; r < 4; r++)
        #pragma unroll
        for (int bb = 0; bb < 4; bb++)
          o[r][bb] = fmaxf(o[r][bb], 0.f);
    }

    // publish to gmem, release per-tile flag
    float* ocell = out_dir + (ri*WW + rj)*CELL;
    #pragma unroll
    for (int r = 0; r < 4; r++)
      *(float4*)(ocell + (c0+r)*BB + b0g) = make_float4(o[r][0], o[r][1], o[r][2], o[r][3]);
    __syncwarp();                                // order warp's STGs before lane0's release
    if (lane == 0) st_rel(mflag, i + 1);

    // vertical state writeback (safe: both v-warps past 2nd idV)
    #pragma unroll
    for (int r = 0; r < 4; r++)
      *(float4*)(hA + (c0+r)*HS + bloc) = make_float4(o[r][0], o[r][1], o[r][2], o[r][3]);

    if (hasLeft && i + 1 < HH) bar64(idA);       // row i closed for the h partner
  }
}

// ---------- kernel 3: out[b][c][i][j] = sum over 4 dirs of g_hf[d][i][j][c][b] ----------
__global__ void __launch_bounds__(256) k_sum(float* __restrict__ out){
  int bid = blockIdx.x;              // 800 blocks: (i, j-tile of 8)
  int i  = bid / 10;
  int j0 = (bid % 10) * 8;
  int t  = threadIdx.x;
  int p0 = t * 8;                    // fixed c, 8 consecutive b
  int c  = p0 >> 5;
  int b0 = p0 & 31;

  float v[8][8];
  #pragma unroll
  for (int jj = 0; jj < 8; jj++){
    int cell = (i*WW + j0 + jj)*CELL;
    float4 s0 = make_float4(0.f,0.f,0.f,0.f);
    float4 s1 = make_float4(0.f,0.f,0.f,0.f);
    #pragma unroll
    for (int d = 0; d < 4; d++){
      const float* src = g_hf[d] + cell + p0;
      float4 q0 = *(const float4*)src;
      float4 q1 = *(const float4*)(src + 4);
      s0.x += q0.x; s0.y += q0.y; s0.z += q0.z; s0.w += q0.w;
      s1.x += q1.x; s1.y += q1.y; s1.z += q1.z; s1.w += q1.w;
    }
    v[0][jj]=s0.x; v[1][jj]=s0.y; v[2][jj]=s0.z; v[3][jj]=s0.w;
    v[4][jj]=s1.x; v[5][jj]=s1.y; v[6][jj]=s1.z; v[7][jj]=s1.w;
  }
  #pragma unroll
  for (int pi = 0; pi < 8; pi++){
    float* dst = out + ((b0+pi)*CC + c)*NCELLS + i*WW + j0;
    *(float4*)dst     = make_float4(v[pi][0], v[pi][1], v[pi][2], v[pi][3]);
    *(float4*)(dst+4) = make_float4(v[pi][4], v[pi][5], v[pi][6], v[pi][7]);
  }
}

extern "C" void kernel_launch(void* const* d_in, const int* in_sizes, int n_in,
                              void* d_out, int out_size){
  const float* x   = (const float*)d_in[0];
  const float* g1  = (const float*)d_in[1];
  const float* g2  = (const float*)d_in[2];
  const float* g4  = (const float*)d_in[3];
  const float* g5  = (const float*)d_in[4];
  const float* g7  = (const float*)d_in[5];
  const float* g8  = (const float*)d_in[6];
  const float* g10 = (const float*)d_in[7];
  const float* g11 = (const float*)d_in[8];

  // G 34,816 + hA 10,240 + hB 20,480 + partial 8,192 = 73,728 B -> 3 CTAs/SM
  const int smem_bytes = 2*CC*GS*4 + 2*CC*HS*4 + 4*CC*HS*4 + 4*256*8;
  (void)cudaFuncSetAttribute(k_dag, cudaFuncAttributeMaxDynamicSharedMemorySize, smem_bytes);

  // two no-op launches: shift ncu's (-s 5 -c 1) capture window onto k_dag
  k_nop<<<1, 1>>>();
  k_nop<<<1, 1>>>();
  k_transpose<<<800, 256>>>(x);
  k_dag<<<4*WW, 256, smem_bytes>>>(g1, g2, g4, g5, g7, g8, g10, g11);
  k_sum<<<800, 256>>>((float*)d_out);
}